// round 8
// baseline (speedup 1.0000x reference)
#include <cuda_runtime.h>

#define NW 10
#define DIM 1024
#define WARPS_PER_BLK 4

typedef unsigned long long u64;

// ---- packed f32x2 primitives ----
__device__ __forceinline__ u64 pk(float x, float y) {
    u64 r; asm("mov.b64 %0,{%1,%2};" : "=l"(r) : "f"(x), "f"(y)); return r;
}
__device__ __forceinline__ u64 pkb(float x) { return pk(x, x); }
__device__ __forceinline__ void upk(u64 a, float& x, float& y) {
    asm("mov.b64 {%0,%1},%2;" : "=f"(x), "=f"(y) : "l"(a));
}
__device__ __forceinline__ float hadd(u64 a) {
    float x, y; upk(a, x, y); return x + y;
}
__device__ __forceinline__ u64 f2fma(u64 a, u64 b, u64 c) {
    u64 d; asm("fma.rn.f32x2 %0,%1,%2,%3;" : "=l"(d) : "l"(a), "l"(b), "l"(c)); return d;
}
__device__ __forceinline__ u64 f2mul(u64 a, u64 b) {
    u64 d; asm("mul.rn.f32x2 %0,%1,%2;" : "=l"(d) : "l"(a), "l"(b)); return d;
}
__device__ __forceinline__ u64 f2add(u64 a, u64 b) {
    u64 d; asm("add.rn.f32x2 %0,%1,%2;" : "=l"(d) : "l"(a), "l"(b)); return d;
}
__device__ __forceinline__ u64 f2sub(u64 a, u64 b) {
    u64 d; asm("sub.rn.f32x2 %0,%1,%2;" : "=l"(d) : "l"(a), "l"(b)); return d;
}
__device__ __forceinline__ u64 swp(u64 a) {      // (re,im)->(im,re)
    float x, y; upk(a, x, y); return pk(y, x);
}
__device__ __forceinline__ u64 ldsv(const u64* p) {   // no cross-gate hoisting
    return *(const volatile u64*)p;
}

// XOR swizzle for conflict-free 32x32 8-byte transpose through shared memory.
__device__ __forceinline__ int swz(int idx) {
    return (idx & 0x3E0) | (((idx >> 5) ^ idx) & 31);
}

// Fused layer-1 gate on register bit K; coefficients loaded (volatile) from shared.
template<int K>
__device__ __forceinline__ void l1c(u64* a, const u64* cf) {
    const u64 arr = ldsv(cf + 0), naiai = ldsv(cf + 1), ainai = ldsv(cf + 2);
    const u64 brr = ldsv(cf + 3), nbrbr = ldsv(cf + 4), nbibi = ldsv(cf + 5);
#pragma unroll
    for (int p = 0; p < 16; ++p) {
        const int m0 = ((p >> K) << (K + 1)) | (p & ((1 << K) - 1));
        const int m1 = m0 | (1 << K);
        u64 a0 = a[m0], a1 = a[m1];
        u64 s0 = swp(a0), s1 = swp(a1);
        u64 n0 = f2fma(arr,   a0, f2fma(naiai, s0, f2fma(brr, a1, f2mul(nbibi, s1))));
        u64 n1 = f2fma(nbrbr, a0, f2fma(nbibi, s0, f2fma(arr, a1, f2mul(ainai, s1))));
        a[m0] = n0; a[m1] = n1;
    }
}

// ============================================================================
// Layer-2 + CNOT folded into the observable (see R7 derivation):
//   E_q = cos(t1_q) * <Z_q>_phi - sin(t1_q) * <X_q>_phi,  phi = CNOT-ring psi
//   <Z_q>: parity-signed prob sums (masks M_b);  <X_q>: coherence sums (masks m_b)
// All X sums are computed as half-sums (each unordered pair once) -> cx = -2 sin.
// LB layout: j = (t<<5)|r.
// ============================================================================

__global__ __launch_bounds__(128, 5)
void qsa8_kernel(const float* __restrict__ x,
                 const float* __restrict__ rx0,
                 const float* __restrict__ ry0,
                 const float* __restrict__ ry1,
                 float* __restrict__ out)
{
    __shared__ u64 buf[WARPS_PER_BLK][DIM];   // 8 KB per warp
    __shared__ u64 cl1[NW][6];                // packed layer-1 coeffs
    __shared__ u64 cw0[4];                    // wire-0 real-input special gate
    __shared__ float cz[NW], cx[NW];          // epilogue combine coeffs

    const int tid = threadIdx.x;
    if (tid < NW) {
        float s, c, s0, c0, s1, c1;
        sincosf(0.5f * rx0[tid], &s,  &c);
        sincosf(0.5f * ry0[tid], &s0, &c0);
        sincosf(0.5f * ry1[tid], &s1, &c1);
        const float ar =  c0 * c;
        const float ai =  s0 * s;
        const float br = -s0 * c;
        const float bi = -c0 * s;
        cl1[tid][0] = pkb(ar);
        cl1[tid][1] = pk(-ai,  ai);
        cl1[tid][2] = pk( ai, -ai);
        cl1[tid][3] = pkb(br);
        cl1[tid][4] = pkb(-br);
        cl1[tid][5] = pk(-bi, bi);
        // cos(theta) = c1^2 - s1^2; sin(theta) = 2 c1 s1; all X sums are half-sums.
        cz[tid] = c1 * c1 - s1 * s1;
        cx[tid] = -4.f * c1 * s1;
        if (tid == 0) {
            cw0[0] = pk( ar,  ai);
            cw0[1] = pk( br,  bi);
            cw0[2] = pk(-br,  bi);
            cw0[3] = pk( ar, -ai);
        }
    }
    __syncthreads();

    const int w = tid >> 5;
    const int t = tid & 31;
    const int n = blockIdx.x * WARPS_PER_BLK + w;   // state 0..4095
    u64* sb = buf[w];

    // ---- Load (LA: i=(r<<5)|t) + packed sumsq ----
    u64 a[32];
    const float* xr = x + (size_t)n * DIM;
    u64 sq = 0ull;
#pragma unroll
    for (int r = 0; r < 32; ++r) {
        a[r] = pkb(xr[(r << 5) + t]);
        sq = f2fma(a[r], a[r], sq);
    }
    float sumsq, dmy;
    upk(sq, sumsq, dmy);
#pragma unroll
    for (int off = 16; off; off >>= 1)
        sumsq += __shfl_xor_sync(0xffffffffu, sumsq, off);
    const float inv = 1.f / fmaxf(sqrtf(sumsq), 1e-12f);

    // ---- Phase A: fused layer-1 on wires 0..4 (wire q -> reg bit K=4-q) ----
    {   // wire 0 (K=4), specialized for purely-real input; normalization folded in.
        const u64 pinv = pkb(inv);
        const u64 pa = f2mul(ldsv(cw0 + 0), pinv), pb = f2mul(ldsv(cw0 + 1), pinv);
        const u64 pc = f2mul(ldsv(cw0 + 2), pinv), pd = f2mul(ldsv(cw0 + 3), pinv);
#pragma unroll
        for (int p = 0; p < 16; ++p) {
            u64 a0 = a[p], a1 = a[p + 16];      // both lanes hold the raw real value
            a[p]      = f2fma(a0, pa, f2mul(a1, pb));
            a[p + 16] = f2fma(a0, pc, f2mul(a1, pd));
        }
    }
    l1c<3>(a, cl1[1]);
    l1c<2>(a, cl1[2]);
    l1c<1>(a, cl1[3]);
    l1c<0>(a, cl1[4]);

    // ---- Remap LA -> LB (transpose) ----
    __syncwarp();
#pragma unroll
    for (int r = 0; r < 32; ++r) sb[swz((r << 5) | t)] = a[r];
    __syncwarp();
#pragma unroll
    for (int r = 0; r < 32; ++r) a[r] = sb[swz((t << 5) | r)];

    // ---- Phase B: fused layer-1 on wires 5..9 (wire q -> reg bit K=9-q) ----
    l1c<4>(a, cl1[5]);
    l1c<3>(a, cl1[6]);
    l1c<2>(a, cl1[7]);
    l1c<1>(a, cl1[8]);
    l1c<0>(a, cl1[9]);

    // ======================= Epilogue on psi (LB: j=(t<<5)|r) ================

    // Z-part: tot + 5 signed r-sums, computed with 2-level butterfly reuse per quad.
    // S10..S1F correspond to r-parity masks 0x10,0x18,0x1C,0x1E,0x1F.
    u64 tot = 0, S10 = 0, S18 = 0, S1C = 0, S1E = 0, S1F = 0;
#pragma unroll
    for (int r = 0; r < 32; r += 4) {
        u64 q0 = f2mul(a[r],     a[r]);
        u64 q1 = f2mul(a[r + 1], a[r + 1]);
        u64 q2 = f2mul(a[r + 2], a[r + 2]);
        u64 q3 = f2mul(a[r + 3], a[r + 3]);
        u64 s01 = f2add(q0, q1), s23 = f2add(q2, q3);
        u64 d01 = f2sub(q0, q1), d23 = f2sub(q2, q3);
        u64 ss = f2add(s01, s23);          // quad sum
        u64 sd = f2sub(s01, s23);          // signed by bit1
        u64 df = f2sub(d01, d23);          // signed by bit0^bit1
        const int pq  = ((r >> 4) ^ (r >> 3) ^ (r >> 2)) & 1;   // parity bits 4..2
        tot = f2add(tot, ss);
        S10 = (r & 0x10)                ? f2sub(S10, ss) : f2add(S10, ss);
        S18 = (((r >> 4) ^ (r >> 3)) & 1) ? f2sub(S18, ss) : f2add(S18, ss);
        S1C = pq ? f2sub(S1C, ss) : f2add(S1C, ss);
        S1E = pq ? f2sub(S1E, sd) : f2add(S1E, sd);
        S1F = pq ? f2sub(S1F, df) : f2add(S1F, df);
    }
    const float tot_s = hadd(tot);
    const float s10 = hadd(S10), s18 = hadd(S18), s1C = hadd(S1C);
    const float s1E = hadd(S1E), s1F = hadd(S1F);

    // X in-register wires 5..8 (partners r^0x18, r^0xC, r^6, r^3), half-sums.
    u64 X5 = 0, X6 = 0, X7 = 0, X8 = 0;
#pragma unroll
    for (int r = 0; r < 32; ++r) {
        if (!(r & 0x10)) X5 = f2fma(a[r], a[r ^ 0x18], X5);
        if (!(r & 0x08)) X6 = f2fma(a[r], a[r ^ 0x0C], X6);
        if (!(r & 0x04)) X7 = f2fma(a[r], a[r ^ 0x06], X7);
        if (!(r & 0x02)) X8 = f2fma(a[r], a[r ^ 0x03], X8);
    }
    const float x5 = hadd(X5), x6 = hadd(X6), x7 = hadd(X7), x8 = hadd(X8);

    // Straddler X wires, half-sums:
    //  w4 (m=0x30): pairs (t, r<16) <-> (t^1, r+16)
    //  w9 (m=0x301): pairs (t, r even) <-> (t^0x18, r+1)
    u64 X4 = 0, X9 = 0;
#pragma unroll
    for (int r = 0; r < 16; ++r) {
        u64 p4 = __shfl_xor_sync(0xffffffffu, a[r + 16], 1);
        X4 = f2fma(a[r], p4, X4);
    }
#pragma unroll
    for (int r = 0; r < 32; r += 2) {
        u64 p9 = __shfl_xor_sync(0xffffffffu, a[r + 1], 0x18);
        X9 = f2fma(a[r], p9, X9);
    }
    const float x4 = hadd(X4), x9 = hadd(X9);

    // ---- Transpose state LB -> LA for wires 0..3 X-terms ----
    __syncwarp();
#pragma unroll
    for (int r = 0; r < 32; ++r) sb[swz((t << 5) | r)] = a[r];
    __syncwarp();
#pragma unroll
    for (int r = 0; r < 32; ++r) a[r] = sb[swz((r << 5) | t)];

    // X in-register wires 0..3 in LA (partners r^0x18, r^0xC, r^6, r^3), half-sums.
    u64 X0 = 0, X1 = 0, X2 = 0, X3 = 0;
#pragma unroll
    for (int r = 0; r < 32; ++r) {
        if (!(r & 0x10)) X0 = f2fma(a[r], a[r ^ 0x18], X0);
        if (!(r & 0x08)) X1 = f2fma(a[r], a[r ^ 0x0C], X1);
        if (!(r & 0x04)) X2 = f2fma(a[r], a[r ^ 0x06], X2);
        if (!(r & 0x02)) X3 = f2fma(a[r], a[r ^ 0x03], X3);
    }
    const float x0 = hadd(X0), x1 = hadd(X1), x2 = hadd(X2), x3 = hadd(X3);

    // Thread-parity signs for the Z parts (t-masks from M_b >> 5).
    const float sgA = (__popc(t & 0x0F) & 1) ? -1.f : 1.f;   // wire 0
    const float sgB = (__popc(t & 0x18) & 1) ? -1.f : 1.f;   // wire 1
    const float sgC = (__popc(t & 0x1C) & 1) ? -1.f : 1.f;   // wire 2
    const float sgD = (__popc(t & 0x1E) & 1) ? -1.f : 1.f;   // wire 3
    const float sgE = (__popc(t & 0x1F) & 1) ? -1.f : 1.f;   // wires 4..9

    // Combine: E_q = cz[q] * Z_q + cx[q] * X_q  (per-thread partials).
    float e[NW];
    e[0] = cz[0] * (sgA * s1F)   + cx[0] * x0;
    e[1] = cz[1] * (sgB * tot_s) + cx[1] * x1;
    e[2] = cz[2] * (sgC * tot_s) + cx[2] * x2;
    e[3] = cz[3] * (sgD * tot_s) + cx[3] * x3;
    e[4] = cz[4] * (sgE * tot_s) + cx[4] * x4;
    e[5] = cz[5] * (sgE * s10)   + cx[5] * x5;
    e[6] = cz[6] * (sgE * s18)   + cx[6] * x6;
    e[7] = cz[7] * (sgE * s1C)   + cx[7] * x7;
    e[8] = cz[8] * (sgE * s1E)   + cx[8] * x8;
    e[9] = cz[9] * (sgE * s1F)   + cx[9] * x9;

    // Packed warp reduction of 10 values as 5 u64.
    u64 vp[5];
#pragma unroll
    for (int j = 0; j < 5; ++j) vp[j] = pk(e[2 * j], e[2 * j + 1]);
#pragma unroll
    for (int off = 16; off; off >>= 1) {
#pragma unroll
        for (int j = 0; j < 5; ++j)
            vp[j] = f2add(vp[j], __shfl_xor_sync(0xffffffffu, vp[j], off));
    }
    if (t == 0) {
#pragma unroll
        for (int j = 0; j < 5; ++j) {
            float vx, vy;
            upk(vp[j], vx, vy);
            out[(size_t)n * NW + 2 * j]     = vx;
            out[(size_t)n * NW + 2 * j + 1] = vy;
        }
    }
}

extern "C" void kernel_launch(void* const* d_in, const int* in_sizes, int n_in,
                              void* d_out, int out_size) {
    const float* x   = (const float*)d_in[0];
    const float* rx0 = (const float*)d_in[1];
    const float* ry0 = (const float*)d_in[2];
    const float* ry1 = (const float*)d_in[3];
    float* out = (float*)d_out;
    const int n_states = in_sizes[0] / DIM;            // 4096
    qsa8_kernel<<<n_states / WARPS_PER_BLK, 32 * WARPS_PER_BLK>>>(x, rx0, ry0, ry1, out);
}

// round 10
// speedup vs baseline: 1.2957x; 1.2957x over previous
#include <cuda_runtime.h>

#define NW 10
#define DIM 1024
#define WARPS_PER_BLK 4

typedef unsigned long long u64;

// ---- packed f32x2 primitives ----
__device__ __forceinline__ u64 pk(float x, float y) {
    u64 r; asm("mov.b64 %0,{%1,%2};" : "=l"(r) : "f"(x), "f"(y)); return r;
}
__device__ __forceinline__ u64 pkb(float x) { return pk(x, x); }
__device__ __forceinline__ void upk(u64 a, float& x, float& y) {
    asm("mov.b64 {%0,%1},%2;" : "=f"(x), "=f"(y) : "l"(a));
}
__device__ __forceinline__ float hadd(u64 a) {
    float x, y; upk(a, x, y); return x + y;
}
__device__ __forceinline__ u64 f2fma(u64 a, u64 b, u64 c) {
    u64 d; asm("fma.rn.f32x2 %0,%1,%2,%3;" : "=l"(d) : "l"(a), "l"(b), "l"(c)); return d;
}
__device__ __forceinline__ u64 f2mul(u64 a, u64 b) {
    u64 d; asm("mul.rn.f32x2 %0,%1,%2;" : "=l"(d) : "l"(a), "l"(b)); return d;
}
__device__ __forceinline__ u64 f2add(u64 a, u64 b) {
    u64 d; asm("add.rn.f32x2 %0,%1,%2;" : "=l"(d) : "l"(a), "l"(b)); return d;
}
__device__ __forceinline__ u64 f2sub(u64 a, u64 b) {
    u64 d; asm("sub.rn.f32x2 %0,%1,%2;" : "=l"(d) : "l"(a), "l"(b)); return d;
}
__device__ __forceinline__ u64 swp(u64 a) {      // (re,im)->(im,re)
    float x, y; upk(a, x, y); return pk(y, x);
}
__device__ __forceinline__ u64 ldsv(const u64* p) {   // no cross-gate hoisting
    return *(const volatile u64*)p;
}

// XOR swizzle for conflict-free 32x32 8-byte transpose through shared memory.
__device__ __forceinline__ int swz(int idx) {
    return (idx & 0x3E0) | (((idx >> 5) ^ idx) & 31);
}

// Fused layer-1 gate on register bit K; coefficients loaded (volatile) from shared.
template<int K>
__device__ __forceinline__ void l1c(u64* a, const u64* cf) {
    const u64 arr = ldsv(cf + 0), naiai = ldsv(cf + 1), ainai = ldsv(cf + 2);
    const u64 brr = ldsv(cf + 3), nbrbr = ldsv(cf + 4), nbibi = ldsv(cf + 5);
#pragma unroll
    for (int p = 0; p < 16; ++p) {
        const int m0 = ((p >> K) << (K + 1)) | (p & ((1 << K) - 1));
        const int m1 = m0 | (1 << K);
        u64 a0 = a[m0], a1 = a[m1];
        u64 s0 = swp(a0), s1 = swp(a1);
        u64 n0 = f2fma(arr,   a0, f2fma(naiai, s0, f2fma(brr, a1, f2mul(nbibi, s1))));
        u64 n1 = f2fma(nbrbr, a0, f2fma(nbibi, s0, f2fma(arr, a1, f2mul(ainai, s1))));
        a[m0] = n0; a[m1] = n1;
    }
}

// ============================================================================
// Layer-2 + CNOT folded into the observable (see R7 derivation):
//   E_q = cos(t1_q) * <Z_q>_phi - sin(t1_q) * <X_q>_phi,  phi = CNOT-ring psi
//   <Z_q>: parity-signed prob sums (masks M_b);  <X_q>: coherence sums (masks m_b)
// All X sums are computed as half-sums (each unordered pair once) -> cx = -4 c1 s1.
// LB layout: j = (t<<5)|r.
// ============================================================================

__global__ __launch_bounds__(128, 4)
void qsa9_kernel(const float* __restrict__ x,
                 const float* __restrict__ rx0,
                 const float* __restrict__ ry0,
                 const float* __restrict__ ry1,
                 float* __restrict__ out)
{
    __shared__ u64 buf[WARPS_PER_BLK][DIM];   // 8 KB per warp
    __shared__ u64 cl1[NW][6];                // packed layer-1 coeffs
    __shared__ u64 cw0[4];                    // wire-0 real-input special gate
    __shared__ float cz[NW], cx[NW];          // epilogue combine coeffs

    const int tid = threadIdx.x;
    if (tid < NW) {
        float s, c, s0, c0, s1, c1;
        sincosf(0.5f * rx0[tid], &s,  &c);
        sincosf(0.5f * ry0[tid], &s0, &c0);
        sincosf(0.5f * ry1[tid], &s1, &c1);
        const float ar =  c0 * c;
        const float ai =  s0 * s;
        const float br = -s0 * c;
        const float bi = -c0 * s;
        cl1[tid][0] = pkb(ar);
        cl1[tid][1] = pk(-ai,  ai);
        cl1[tid][2] = pk( ai, -ai);
        cl1[tid][3] = pkb(br);
        cl1[tid][4] = pkb(-br);
        cl1[tid][5] = pk(-bi, bi);
        // cos(theta) = c1^2 - s1^2; sin(theta) = 2 c1 s1; all X sums are half-sums.
        cz[tid] = c1 * c1 - s1 * s1;
        cx[tid] = -4.f * c1 * s1;
        if (tid == 0) {
            cw0[0] = pk( ar,  ai);
            cw0[1] = pk( br,  bi);
            cw0[2] = pk(-br,  bi);
            cw0[3] = pk( ar, -ai);
        }
    }
    __syncthreads();

    const int w = tid >> 5;
    const int t = tid & 31;
    const int n = blockIdx.x * WARPS_PER_BLK + w;   // state 0..4095
    u64* sb = buf[w];

    // ---- Load (LA: i=(r<<5)|t) + packed sumsq ----
    u64 a[32];
    const float* xr = x + (size_t)n * DIM;
    u64 sq = 0ull;
#pragma unroll
    for (int r = 0; r < 32; ++r) {
        a[r] = pkb(xr[(r << 5) + t]);
        sq = f2fma(a[r], a[r], sq);
    }
    float sumsq, dmy;
    upk(sq, sumsq, dmy);
#pragma unroll
    for (int off = 16; off; off >>= 1)
        sumsq += __shfl_xor_sync(0xffffffffu, sumsq, off);
    const float inv = 1.f / fmaxf(sqrtf(sumsq), 1e-12f);

    // ---- Phase A: fused layer-1 on wires 0..4 (wire q -> reg bit K=4-q) ----
    {   // wire 0 (K=4), specialized for purely-real input; normalization folded in.
        const u64 pinv = pkb(inv);
        const u64 pa = f2mul(ldsv(cw0 + 0), pinv), pb = f2mul(ldsv(cw0 + 1), pinv);
        const u64 pc = f2mul(ldsv(cw0 + 2), pinv), pd = f2mul(ldsv(cw0 + 3), pinv);
#pragma unroll
        for (int p = 0; p < 16; ++p) {
            u64 a0 = a[p], a1 = a[p + 16];      // both lanes hold the raw real value
            a[p]      = f2fma(a0, pa, f2mul(a1, pb));
            a[p + 16] = f2fma(a0, pc, f2mul(a1, pd));
        }
    }
    l1c<3>(a, cl1[1]);
    l1c<2>(a, cl1[2]);
    l1c<1>(a, cl1[3]);
    l1c<0>(a, cl1[4]);

    // ---- Remap LA -> LB (transpose) ----
    __syncwarp();
#pragma unroll
    for (int r = 0; r < 32; ++r) sb[swz((r << 5) | t)] = a[r];
    __syncwarp();
#pragma unroll
    for (int r = 0; r < 32; ++r) a[r] = sb[swz((t << 5) | r)];

    // ---- Phase B: fused layer-1 on wires 5..9 (wire q -> reg bit K=9-q) ----
    l1c<4>(a, cl1[5]);
    l1c<3>(a, cl1[6]);
    l1c<2>(a, cl1[7]);
    l1c<1>(a, cl1[8]);
    l1c<0>(a, cl1[9]);

    // ======================= Epilogue on psi (LB: j=(t<<5)|r) ================

    // Z-part: tot + 5 signed r-sums, computed with 2-level butterfly reuse per quad.
    // S10..S1F correspond to r-parity masks 0x10,0x18,0x1C,0x1E,0x1F.
    u64 tot = 0, S10 = 0, S18 = 0, S1C = 0, S1E = 0, S1F = 0;
#pragma unroll
    for (int r = 0; r < 32; r += 4) {
        u64 q0 = f2mul(a[r],     a[r]);
        u64 q1 = f2mul(a[r + 1], a[r + 1]);
        u64 q2 = f2mul(a[r + 2], a[r + 2]);
        u64 q3 = f2mul(a[r + 3], a[r + 3]);
        u64 s01 = f2add(q0, q1), s23 = f2add(q2, q3);
        u64 d01 = f2sub(q0, q1), d23 = f2sub(q2, q3);
        u64 ss = f2add(s01, s23);          // quad sum
        u64 sd = f2sub(s01, s23);          // signed by bit1
        u64 df = f2sub(d01, d23);          // signed by bit0^bit1
        const int pq  = ((r >> 4) ^ (r >> 3) ^ (r >> 2)) & 1;   // parity bits 4..2
        tot = f2add(tot, ss);
        S10 = (r & 0x10)                  ? f2sub(S10, ss) : f2add(S10, ss);
        S18 = (((r >> 4) ^ (r >> 3)) & 1) ? f2sub(S18, ss) : f2add(S18, ss);
        S1C = pq ? f2sub(S1C, ss) : f2add(S1C, ss);
        S1E = pq ? f2sub(S1E, sd) : f2add(S1E, sd);
        S1F = pq ? f2sub(S1F, df) : f2add(S1F, df);
    }
    const float tot_s = hadd(tot);
    const float s10 = hadd(S10), s18 = hadd(S18), s1C = hadd(S1C);
    const float s1E = hadd(S1E), s1F = hadd(S1F);

    // X in-register wires 5..8 (partners r^0x18, r^0xC, r^6, r^3), half-sums.
    u64 X5 = 0, X6 = 0, X7 = 0, X8 = 0;
#pragma unroll
    for (int r = 0; r < 32; ++r) {
        if (!(r & 0x10)) X5 = f2fma(a[r], a[r ^ 0x18], X5);
        if (!(r & 0x08)) X6 = f2fma(a[r], a[r ^ 0x0C], X6);
        if (!(r & 0x04)) X7 = f2fma(a[r], a[r ^ 0x06], X7);
        if (!(r & 0x02)) X8 = f2fma(a[r], a[r ^ 0x03], X8);
    }
    const float x5 = hadd(X5), x6 = hadd(X6), x7 = hadd(X7), x8 = hadd(X8);

    // Straddler X wires, half-sums:
    //  w4 (m=0x30): pairs (t, r<16) <-> (t^1, r+16)
    //  w9 (m=0x301): pairs (t, r even) <-> (t^0x18, r+1)
    u64 X4 = 0, X9 = 0;
#pragma unroll
    for (int r = 0; r < 16; ++r) {
        u64 p4 = __shfl_xor_sync(0xffffffffu, a[r + 16], 1);
        X4 = f2fma(a[r], p4, X4);
    }
#pragma unroll
    for (int r = 0; r < 32; r += 2) {
        u64 p9 = __shfl_xor_sync(0xffffffffu, a[r + 1], 0x18);
        X9 = f2fma(a[r], p9, X9);
    }
    const float x4 = hadd(X4), x9 = hadd(X9);

    // ---- Transpose state LB -> LA for wires 0..3 X-terms ----
    __syncwarp();
#pragma unroll
    for (int r = 0; r < 32; ++r) sb[swz((t << 5) | r)] = a[r];
    __syncwarp();
#pragma unroll
    for (int r = 0; r < 32; ++r) a[r] = sb[swz((r << 5) | t)];

    // X in-register wires 0..3 in LA (partners r^0x18, r^0xC, r^6, r^3), half-sums.
    u64 X0 = 0, X1 = 0, X2 = 0, X3 = 0;
#pragma unroll
    for (int r = 0; r < 32; ++r) {
        if (!(r & 0x10)) X0 = f2fma(a[r], a[r ^ 0x18], X0);
        if (!(r & 0x08)) X1 = f2fma(a[r], a[r ^ 0x0C], X1);
        if (!(r & 0x04)) X2 = f2fma(a[r], a[r ^ 0x06], X2);
        if (!(r & 0x02)) X3 = f2fma(a[r], a[r ^ 0x03], X3);
    }
    const float x0 = hadd(X0), x1 = hadd(X1), x2 = hadd(X2), x3 = hadd(X3);

    // Thread-parity signs for the Z parts (t-masks from M_b >> 5).
    const float sgA = (__popc(t & 0x0F) & 1) ? -1.f : 1.f;   // wire 0
    const float sgB = (__popc(t & 0x18) & 1) ? -1.f : 1.f;   // wire 1
    const float sgC = (__popc(t & 0x1C) & 1) ? -1.f : 1.f;   // wire 2
    const float sgD = (__popc(t & 0x1E) & 1) ? -1.f : 1.f;   // wire 3
    const float sgE = (__popc(t & 0x1F) & 1) ? -1.f : 1.f;   // wires 4..9

    // Combine: E_q = cz[q] * Z_q + cx[q] * X_q  (per-thread partials).
    float e[NW];
    e[0] = cz[0] * (sgA * s1F)   + cx[0] * x0;
    e[1] = cz[1] * (sgB * tot_s) + cx[1] * x1;
    e[2] = cz[2] * (sgC * tot_s) + cx[2] * x2;
    e[3] = cz[3] * (sgD * tot_s) + cx[3] * x3;
    e[4] = cz[4] * (sgE * tot_s) + cx[4] * x4;
    e[5] = cz[5] * (sgE * s10)   + cx[5] * x5;
    e[6] = cz[6] * (sgE * s18)   + cx[6] * x6;
    e[7] = cz[7] * (sgE * s1C)   + cx[7] * x7;
    e[8] = cz[8] * (sgE * s1E)   + cx[8] * x8;
    e[9] = cz[9] * (sgE * s1F)   + cx[9] * x9;

    // Packed warp reduction of 10 values as 5 u64.
    u64 vp[5];
#pragma unroll
    for (int j = 0; j < 5; ++j) vp[j] = pk(e[2 * j], e[2 * j + 1]);
#pragma unroll
    for (int off = 16; off; off >>= 1) {
#pragma unroll
        for (int j = 0; j < 5; ++j)
            vp[j] = f2add(vp[j], __shfl_xor_sync(0xffffffffu, vp[j], off));
    }
    if (t == 0) {
#pragma unroll
        for (int j = 0; j < 5; ++j) {
            float vx, vy;
            upk(vp[j], vx, vy);
            out[(size_t)n * NW + 2 * j]     = vx;
            out[(size_t)n * NW + 2 * j + 1] = vy;
        }
    }
}

extern "C" void kernel_launch(void* const* d_in, const int* in_sizes, int n_in,
                              void* d_out, int out_size) {
    const float* x   = (const float*)d_in[0];
    const float* rx0 = (const float*)d_in[1];
    const float* ry0 = (const float*)d_in[2];
    const float* ry1 = (const float*)d_in[3];
    float* out = (float*)d_out;
    const int n_states = in_sizes[0] / DIM;            // 4096
    qsa9_kernel<<<n_states / WARPS_PER_BLK, 32 * WARPS_PER_BLK>>>(x, rx0, ry0, ry1, out);
}